// round 4
// baseline (speedup 1.0000x reference)
#include <cuda_runtime.h>
#include <cuda_bf16.h>
#include <cstdint>

// Problem constants (fixed by the reference setup_inputs)
#define B_  128
#define L_  2048
#define H_  768
#define H4_ 192          // H / 4 floats per float4
#define CHUNK_ROWS 128
#define NCHUNKS (L_ / CHUNK_ROWS)   // 16

// Clamped inclusive span [start, end] for batch b, span s (0=head,1=tail).
// JAX x64 is disabled by default -> entity_positions arrives as int32.
__device__ __forceinline__ void span_bounds(const int* __restrict__ pos,
                                            int b, int s, int& start, int& end) {
    int p0 = pos[b * 4 + s * 2];
    int p1 = pos[b * 4 + s * 2 + 1];
    int st = p0 < 0 ? 0 : (p0 > (L_ - 1) ? (L_ - 1) : p0);
    int en = p1 > (L_ - 1) ? (L_ - 1) : p1;
    if (en < st) en = st;
    start = st;
    end   = en;
}

// One block per (L-chunk, batch). Reads each row in the union of the two
// span-chunk intersections once. Per-row scalar weights (0 or 1/count) make
// the loads unconditional so ptxas front-batches 8 independent LDG.128 per
// iteration (MLP=8). Scaled partials are atomicAdd'ed into d_out.
__global__ void __launch_bounds__(H4_)
entity_accum_kernel(const float4* __restrict__ seq4,
                    const int* __restrict__ pos,
                    float* __restrict__ out) {
    const int c = blockIdx.x;
    const int b = blockIdx.y;

    int hs, he, ts, te;
    span_bounds(pos, b, 0, hs, he);
    span_bounds(pos, b, 1, ts, te);

    const int clo = c * CHUNK_ROWS;
    const int chi = clo + CHUNK_ROWS - 1;

    const int hlo = max(hs, clo), hhi = min(he, chi);
    const int tlo = max(ts, clo), thi = min(te, chi);
    const bool doH = hlo <= hhi;
    const bool doT = tlo <= thi;
    if (!doH && !doT) return;

    int lo, hi;
    if (doH && doT) { lo = min(hlo, tlo); hi = max(hhi, thi); }
    else if (doH)   { lo = hlo; hi = hhi; }
    else            { lo = tlo; hi = thi; }

    const float invH = doH ? 1.0f / (float)(he - hs + 1) : 0.0f;
    const float invT = doT ? 1.0f / (float)(te - ts + 1) : 0.0f;

    const int t = threadIdx.x;  // 0..191
    const float4* base = seq4 + (size_t)b * L_ * H4_ + t;

    float4 aH = make_float4(0.f, 0.f, 0.f, 0.f);
    float4 aT = make_float4(0.f, 0.f, 0.f, 0.f);

    int r = lo;
    // 8-row batched main loop: 8 independent unconditional loads per iter.
    for (; r + 7 <= hi; r += 8) {
        float4 v[8];
        #pragma unroll
        for (int i = 0; i < 8; ++i)
            v[i] = __ldg(base + (size_t)(r + i) * H4_);
        #pragma unroll
        for (int i = 0; i < 8; ++i) {
            const int rr = r + i;
            const float wH = ((rr >= hlo) & (rr <= hhi)) ? invH : 0.0f;
            const float wT = ((rr >= tlo) & (rr <= thi)) ? invT : 0.0f;
            aH.x += v[i].x * wH; aH.y += v[i].y * wH;
            aH.z += v[i].z * wH; aH.w += v[i].w * wH;
            aT.x += v[i].x * wT; aT.y += v[i].y * wT;
            aT.z += v[i].z * wT; aT.w += v[i].w * wT;
        }
    }
    for (; r <= hi; ++r) {
        float4 v = __ldg(base + (size_t)r * H4_);
        const float wH = ((r >= hlo) & (r <= hhi)) ? invH : 0.0f;
        const float wT = ((r >= tlo) & (r <= thi)) ? invT : 0.0f;
        aH.x += v.x * wH; aH.y += v.y * wH; aH.z += v.z * wH; aH.w += v.w * wH;
        aT.x += v.x * wT; aT.y += v.y * wT; aT.z += v.z * wT; aT.w += v.w * wT;
    }

    if (doH) {
        float* o = out + (size_t)b * H_ + (size_t)t * 4;          // head slab
        atomicAdd(o + 0, aH.x);
        atomicAdd(o + 1, aH.y);
        atomicAdd(o + 2, aH.z);
        atomicAdd(o + 3, aH.w);
    }
    if (doT) {
        float* o = out + (size_t)(B_ + b) * H_ + (size_t)t * 4;   // tail slab
        atomicAdd(o + 0, aT.x);
        atomicAdd(o + 1, aT.y);
        atomicAdd(o + 2, aT.z);
        atomicAdd(o + 3, aT.w);
    }
}

extern "C" void kernel_launch(void* const* d_in, const int* in_sizes, int n_in,
                              void* d_out, int out_size) {
    const float4* seq4 = (const float4*)d_in[0];   // [B, L, H] fp32
    const int*    pos  = (const int*)d_in[1];      // [B, 4] int32
    float* out = (float*)d_out;                     // [2, B, H] fp32

    // Zero the accumulation target (d_out is poisoned before timing).
    cudaMemsetAsync(d_out, 0, (size_t)2 * B_ * H_ * sizeof(float));

    dim3 grid(NCHUNKS, B_);
    entity_accum_kernel<<<grid, H4_>>>(seq4, pos, out);
}

// round 5
// speedup vs baseline: 1.2530x; 1.2530x over previous
#include <cuda_runtime.h>
#include <cuda_bf16.h>
#include <cstdint>

// Problem constants (fixed by the reference setup_inputs)
#define B_  128
#define L_  2048
#define H_  768
#define H4_ 192          // H / 4 floats per float4
#define CHUNK_ROWS 128
#define NCHUNKS (L_ / CHUNK_ROWS)   // 16

// Clamped inclusive span [start, end] for batch b, span s (0=head,1=tail).
// JAX x64 is disabled by default -> entity_positions arrives as int32.
__device__ __forceinline__ void span_bounds(const int* __restrict__ pos,
                                            int b, int s, int& start, int& end) {
    int p0 = pos[b * 4 + s * 2];
    int p1 = pos[b * 4 + s * 2 + 1];
    int st = p0 < 0 ? 0 : (p0 > (L_ - 1) ? (L_ - 1) : p0);
    int en = p1 > (L_ - 1) ? (L_ - 1) : p1;
    if (en < st) en = st;
    start = st;
    end   = en;
}

// One block per (L-chunk, batch, span). Simple 4-wide batched load loop
// (proven ~6.4 TB/s shape from R2), partial scaled by 1/count, atomicAdd
// into d_out. No finalize kernel.
__global__ void __launch_bounds__(H4_)
entity_accum_kernel(const float4* __restrict__ seq4,
                    const int* __restrict__ pos,
                    float* __restrict__ out) {
    const int c = blockIdx.x;
    const int b = blockIdx.y;
    const int s = blockIdx.z;

    int start, end;
    span_bounds(pos, b, s, start, end);

    const int lo = max(start, c * CHUNK_ROWS);
    const int hi = min(end,   c * CHUNK_ROWS + CHUNK_ROWS - 1);
    if (lo > hi) return;

    const float inv = 1.0f / (float)(end - start + 1);

    const int t = threadIdx.x;  // 0..191
    const float4* base = seq4 + (size_t)b * L_ * H4_ + t;

    float4 acc = make_float4(0.f, 0.f, 0.f, 0.f);

    int r = lo;
    // 4-row batched main loop: 4 independent LDG.128 in flight per thread.
    for (; r + 3 <= hi; r += 4) {
        float4 v0 = __ldg(base + (size_t)(r + 0) * H4_);
        float4 v1 = __ldg(base + (size_t)(r + 1) * H4_);
        float4 v2 = __ldg(base + (size_t)(r + 2) * H4_);
        float4 v3 = __ldg(base + (size_t)(r + 3) * H4_);
        acc.x += v0.x + v1.x + v2.x + v3.x;
        acc.y += v0.y + v1.y + v2.y + v3.y;
        acc.z += v0.z + v1.z + v2.z + v3.z;
        acc.w += v0.w + v1.w + v2.w + v3.w;
    }
    for (; r <= hi; ++r) {
        float4 v = __ldg(base + (size_t)r * H4_);
        acc.x += v.x; acc.y += v.y; acc.z += v.z; acc.w += v.w;
    }

    float* o = out + ((size_t)s * B_ + b) * H_ + (size_t)t * 4;
    atomicAdd(o + 0, acc.x * inv);
    atomicAdd(o + 1, acc.y * inv);
    atomicAdd(o + 2, acc.z * inv);
    atomicAdd(o + 3, acc.w * inv);
}

extern "C" void kernel_launch(void* const* d_in, const int* in_sizes, int n_in,
                              void* d_out, int out_size) {
    const float4* seq4 = (const float4*)d_in[0];   // [B, L, H] fp32
    const int*    pos  = (const int*)d_in[1];      // [B, 4] int32
    float* out = (float*)d_out;                     // [2, B, H] fp32

    // Zero the accumulation target (d_out is poisoned before timing).
    cudaMemsetAsync(d_out, 0, (size_t)2 * B_ * H_ * sizeof(float));

    dim3 grid(NCHUNKS, B_, 2);
    entity_accum_kernel<<<grid, H4_>>>(seq4, pos, out);
}